// round 8
// baseline (speedup 1.0000x reference)
#include <cuda_runtime.h>
#include <cuda_bf16.h>
#include <cstdint>

#define B_    32
#define CIN_  12
#define LEN_  1024
#define TT_   64
#define C1_   64
#define C2_   128

// Scratch (device globals; no runtime allocation)
__device__ float    g_xT[TT_ * B_ * CIN_ * LEN_];   // [t][b][cin][l]
__device__ uint4    g_Apk[7168];     // packed s8 w2 frags [c2h][plane][mi][chunk][lane]
__device__ unsigned g_Alo[2 * 3584]; // lo plane (h=1) words [c2h][koff][c1w][m]
__device__ float2   g_w1pk[84 * 32]; // conv1 weight pairs
__device__ float    g_pool[B_ * C2_];

typedef unsigned long long u64;

// ---- packed f32x2 helpers ----
__device__ __forceinline__ u64 pack2(float lo, float hi) {
    u64 r;
    asm("mov.b64 %0, {%1, %2};" : "=l"(r) : "f"(lo), "f"(hi));
    return r;
}
__device__ __forceinline__ void unpack2(u64 v, float& lo, float& hi) {
    asm("mov.b64 {%0, %1}, %2;" : "=f"(lo), "=f"(hi) : "l"(v));
}
__device__ __forceinline__ void ffma2(u64& d, u64 a, u64 b) {
    asm("fma.rn.f32x2 %0, %1, %2, %0;" : "+l"(d) : "l"(a), "l"(b));
}
__device__ __forceinline__ void dp4a(int& acc, unsigned a, unsigned b) {
    asm("dp4a.s32.s32 %0, %1, %2, %0;" : "+r"(acc) : "r"(a), "r"(b));
}

// ---- warp MMA: m16n8k32 s8.s8.s32 ----
#define IMMA16832(D, A, B0, B1)                                              \
    asm volatile(                                                            \
        "mma.sync.aligned.m16n8k32.row.col.s32.s8.s8.s32 "                   \
        "{%0,%1,%2,%3}, {%4,%5,%6,%7}, {%8,%9}, {%0,%1,%2,%3};"              \
        : "+r"((D)[0]), "+r"((D)[1]), "+r"((D)[2]), "+r"((D)[3])             \
        : "r"((A).x), "r"((A).y), "r"((A).z), "r"((A).w), "r"(B0), "r"(B1))

// ============================================================================
// Kernel A: quantize + pack w2. Exact 2-plane split at scale 2^15:
// q = round(w*2^15); hi = (q+128)>>8; lo = q - hi*256 (both s8, q = hi*256+lo).
// Outputs: g_Apk (IMMA frags) and g_Alo (h=1 lo words for dp4a).
// ============================================================================
__global__ void __launch_bounds__(256) w2prep_kernel(const float* __restrict__ w2) {
    int idx = blockIdx.x * 256 + threadIdx.x;
    if (idx >= 7168) return;

    // ---- IMMA fragment packing ----
    {
        int lane = idx & 31;
        int r    = idx >> 5;
        int chunk = r % 14;
        int r2    = r / 14;
        int mi    = r2 & 3;
        int plane = (r2 >> 2) & 1;
        int c2h   = r2 >> 3;
        int g = lane >> 2, c = lane & 3;
        int h = chunk & 1, koff = chunk >> 1;
        int m0 = c2h * 64 + mi * 16;
        int c1b = 32 * h + 4 * c;

        auto pk4 = [&](int m, int c1s) -> unsigned {
            unsigned rr = 0;
#pragma unroll
            for (int j = 0; j < 4; ++j) {
                float w = w2[m * 448 + (c1s + j) * 7 + koff];
                int q = __float2int_rn(w * 32768.f);
                int hi = (q + 128) >> 8;
                int lo = q - (hi << 8);
                int val = plane ? lo : hi;
                rr |= ((unsigned)(val & 0xFF)) << (8 * j);
            }
            return rr;
        };
        uint4 out;
        out.x = pk4(m0 + g,     c1b);
        out.y = pk4(m0 + g + 8, c1b);
        out.z = pk4(m0 + g,     c1b + 16);
        out.w = pk4(m0 + g + 8, c1b + 16);
        g_Apk[idx] = out;
    }

    // ---- dp4a lo words (h=1 half: c1 in [32,64)) ----
    {
        int c2h  = idx / 3584;
        int rem  = idx % 3584;
        int koff = rem >> 9;            // 0..6
        int c1w  = (rem >> 6) & 7;      // 0..7
        int mloc = rem & 63;
        int m = c2h * 64 + mloc;
        unsigned rr = 0;
#pragma unroll
        for (int j = 0; j < 4; ++j) {
            int c1 = 32 + 4 * c1w + j;
            float w = w2[m * 448 + c1 * 7 + koff];
            int q = __float2int_rn(w * 32768.f);
            int hi = (q + 128) >> 8;
            int lo = q - (hi << 8);
            rr |= ((unsigned)(lo & 0xFF)) << (8 * j);
        }
        g_Alo[idx] = rr;
    }
}

// ============================================================================
// Kernel B: transpose x [b][cin][l][t] -> g_xT [t][b][cin][l]
// ============================================================================
__global__ void __launch_bounds__(256) transpose_kernel(const float* __restrict__ x) {
    __shared__ float tile[32][33];
    const int bc = blockIdx.z;
    const int t0 = blockIdx.x * 32;
    const int l0 = blockIdx.y * 32;
    const int tx = threadIdx.x;
    const int ty = threadIdx.y;
    const float* xb = x + (size_t)bc * LEN_ * TT_;
#pragma unroll
    for (int j = 0; j < 4; ++j)
        tile[ty + j * 8][tx] = xb[(size_t)(l0 + ty + j * 8) * TT_ + t0 + tx];
    __syncthreads();
#pragma unroll
    for (int j = 0; j < 4; ++j)
        g_xT[((size_t)(t0 + ty + j * 8) * (B_ * CIN_) + bc) * LEN_ + l0 + tx] =
            tile[tx][ty + j * 8];
}

// ============================================================================
// Kernel C: pack w1 pairs + zero g_pool (fused kernel stays launch #4)
// ============================================================================
__global__ void __launch_bounds__(256) w1prep_kernel(const float* __restrict__ w1) {
    int idx = blockIdx.x * 256 + threadIdx.x;
    if (idx < B_ * C2_) g_pool[idx] = 0.f;
    if (idx < 84 * 32) {
        int r = idx >> 5, i = idx & 31;
        float2 p;
        p.x = w1[(2 * i) * 84 + r];
        p.y = w1[(2 * i + 1) * 84 + r];
        g_w1pk[idx] = p;
    }
}

// ============================================================================
// Kernel D (FUSED): conv1(FFMA2)+LIF1 + conv2(IMMA hi+lo_h0 / dp4a lo_h1)
// + LIF2. ANTI-PHASE warp scheduling: odd warps run (conv1 -> dp4a -> IMMA),
// even warps run (IMMA -> dp4a -> conv1), so the tensor and fma pipes are
// both fed at every instant instead of convoying.
// ============================================================================
#define SPT_PITCH 80
#define OFF_SA   0                       //  57344 B  IMMA A frags
#define OFF_ALO  57344                   //  14336 B  dp4a lo words
#define OFF_SPT0 (OFF_ALO + 14336)       //   5760 B
#define OFF_SPT1 (OFF_SPT0 + 5760)       //   5760 B
#define OFF_XS0  (OFF_SPT1 + 5760)       //   3840 B
#define OFF_XS1  (OFF_XS0 + 3840)        //   3840 B
#define OFF_WS1  (OFF_XS1 + 3840)        //  21504 B
#define SMEM_SZ  (OFF_WS1 + 21504)       // 112384 B
#define APK_U4   3584

extern __shared__ char fsm[];

__global__ void __launch_bounds__(256, 2)
fused_kernel(const float* __restrict__ b1, const float* __restrict__ b2) {
    const int tid  = threadIdx.x;
    const int wid  = tid >> 5;
    const int lane = tid & 31;
    const int wy = wid >> 2;        // 0..1  M group of 32
    const int wx = wid & 3;         // 0..3  N group of 16
    const int g  = lane >> 2;
    const int c  = lane & 3;
    const int lt  = blockIdx.x;     // 0..15
    const int c2h = blockIdx.y;     // 0..1
    const int b   = blockIdx.z;     // 0..31
    const int l0  = lt * 64;

    uint4*    sA   = reinterpret_cast<uint4*>(fsm + OFF_SA);
    unsigned* sAlo = reinterpret_cast<unsigned*>(fsm + OFF_ALO);
    char*     spt[2] = {fsm + OFF_SPT0, fsm + OFF_SPT1};
    float*    xs[2]  = {reinterpret_cast<float*>(fsm + OFF_XS0),
                        reinterpret_cast<float*>(fsm + OFF_XS1)};
    float2*   ws1 = reinterpret_cast<float2*>(fsm + OFF_WS1);

    // ---- one-time staging ----
    {
        const uint4* gA = g_Apk + c2h * APK_U4;
#pragma unroll 7
        for (int i = tid; i < APK_U4; i += 256) sA[i] = gA[i];
        const unsigned* gL = g_Alo + c2h * 3584;
#pragma unroll 7
        for (int i = tid; i < 3584; i += 256) sAlo[i] = gL[i];
#pragma unroll 2
        for (int i = tid; i < 84 * 32; i += 256) ws1[i] = g_w1pk[i];
    }

    auto ldg_xs = [&](int t) -> float4 {
        float4 v = make_float4(0.f, 0.f, 0.f, 0.f);
        if (tid < 240 && t < TT_) {
            int cin = tid / 20, q = tid % 20;
            int l = l0 - 8 + q * 4;
            if (l >= 0 && l + 3 < LEN_) {
                v = *reinterpret_cast<const float4*>(
                    g_xT + ((size_t)((t * B_ + b) * CIN_) + cin) * LEN_ + l);
            }
        }
        return v;
    };
    auto sts_xs = [&](float4 v, float* buf) {
        if (tid < 240) {
            int cin = tid / 20, q = tid % 20;
            *reinterpret_cast<float4*>(buf + cin * 80 + q * 4) = v;
        }
    };

    float4 st0 = ldg_xs(0);
    sts_xs(st0, xs[0]);

    const float b1lo = b1[2 * lane];
    const float b1hi = b1[2 * lane + 1];

    // conv1 for one timestep: xs buf -> spike tile
    auto conv1_step = [&](const float* xsb, char* sptb) {
        const int jb = wid * 9;
        u64 acc[9];
#pragma unroll
        for (int r = 0; r < 9; ++r) acc[r] = 0ull;
#pragma unroll 1
        for (int cin = 0; cin < 12; ++cin) {
            const float* xr = xsb + cin * 80 + jb + 2;
            u64 pv[15];
#pragma unroll
            for (int m = 0; m < 15; ++m) {
                float xv = xr[m];
                pv[m] = pack2(xv, xv);
            }
#pragma unroll
            for (int k = 0; k < 7; ++k) {
                float2 wp = ws1[(cin * 7 + k) * 32 + lane];
                u64 wpk = pack2(wp.x, wp.y);
#pragma unroll
                for (int r = 0; r < 9; ++r)
                    ffma2(acc[r], pv[r + k], wpk);
            }
        }
#pragma unroll
        for (int r = 0; r < 9; ++r) {
            int j = jb + r;
            int l = l0 - 3 + j;
            float v0, v1;
            unpack2(acc[r], v0, v1);
            bool in = ((unsigned)l < (unsigned)LEN_);
            unsigned s0 = (in && 2.f * (v0 + b1lo) >= 0.5f) ? 1u : 0u;
            unsigned s1 = (in && 2.f * (v1 + b1hi) >= 0.5f) ? 1u : 0u;
            *reinterpret_cast<unsigned short*>(sptb + j * SPT_PITCH + 2 * lane) =
                (unsigned short)(s0 | (s1 << 8));
        }
    };

    __syncthreads();            // staging + xs(0) visible
    conv1_step(xs[0], spt[0]);  // spikes for t=0
    float4 st1 = ldg_xs(1);
    sts_xs(st1, xs[1]);
    __syncthreads();            // spT(0) + xs(1) visible

    float bb[2][2];
#pragma unroll
    for (int mt = 0; mt < 2; ++mt)
#pragma unroll
        for (int hf = 0; hf < 2; ++hf)
            bb[mt][hf] = 2.f * b2[c2h * 64 + wy * 32 + mt * 16 + g + hf * 8];

    float v[2][2][4];
#pragma unroll
    for (int mt = 0; mt < 2; ++mt)
#pragma unroll
        for (int nt = 0; nt < 2; ++nt)
#pragma unroll
            for (int e = 0; e < 4; ++e) v[mt][nt][e] = 0.f;
    float accs[2][2] = {{0.f, 0.f}, {0.f, 0.f}};

    const float SCALE = 6.103515625e-05f;   // 2^-14
    const float INV_TAU = 1.0f / 0.9f;
    const bool  rev = (wid & 1);             // anti-phase warps

#pragma unroll 1
    for (int t = 0; t < TT_; ++t) {
        const char* curB = spt[t & 1];

        float4 stg = ldg_xs(t + 2);   // early: hides under compute

        int dh[2][2][4], dl[2][2][4], ds[2][2][4];
#pragma unroll
        for (int mt = 0; mt < 2; ++mt)
#pragma unroll
            for (int nt = 0; nt < 2; ++nt)
#pragma unroll
                for (int e = 0; e < 4; ++e) {
                    dh[mt][nt][e] = 0; dl[mt][nt][e] = 0; ds[mt][nt][e] = 0;
                }

        // ---- phase bodies ----
        auto tensor_phase = [&]() {
#pragma unroll 1
            for (int koff = 0; koff < 7; ++koff) {
                const int ch0 = koff * 2, ch1 = ch0 + 1;
                uint4 ah0[2], ah1[2], al0[2];
#pragma unroll
                for (int mt = 0; mt < 2; ++mt) {
                    int mi = wy * 2 + mt;
                    ah0[mt] = sA[((0 + mi) * 14 + ch0) * 32 + lane];
                    ah1[mt] = sA[((0 + mi) * 14 + ch1) * 32 + lane];
                    al0[mt] = sA[((4 + mi) * 14 + ch0) * 32 + lane];
                }
                const char* brow = curB + (size_t)(wx * 16 + g + koff) * SPT_PITCH + c * 4;
                unsigned b00[2], b01[2], b10[2], b11[2];
#pragma unroll
                for (int nt = 0; nt < 2; ++nt) {
                    const char* p = brow + nt * 8 * SPT_PITCH;
                    b00[nt] = *reinterpret_cast<const unsigned*>(p);
                    b01[nt] = *reinterpret_cast<const unsigned*>(p + 16);
                    b10[nt] = *reinterpret_cast<const unsigned*>(p + 32);
                    b11[nt] = *reinterpret_cast<const unsigned*>(p + 48);
                }
#pragma unroll
                for (int nt = 0; nt < 2; ++nt) {
                    IMMA16832(dh[0][nt], ah0[0], b00[nt], b01[nt]);
                    IMMA16832(dh[1][nt], ah0[1], b00[nt], b01[nt]);
                    IMMA16832(dh[0][nt], ah1[0], b10[nt], b11[nt]);
                    IMMA16832(dh[1][nt], ah1[1], b10[nt], b11[nt]);
                    IMMA16832(dl[0][nt], al0[0], b00[nt], b01[nt]);
                    IMMA16832(dl[1][nt], al0[1], b00[nt], b01[nt]);
                }
            }
        };
        auto alu_phase = [&]() {
#pragma unroll 1
            for (int koff = 0; koff < 7; ++koff) {
                const char* bbase = curB + (size_t)(wx * 16 + 2 * c + koff) * SPT_PITCH + 32;
                const unsigned* abase = sAlo + koff * 512 + wy * 32 + g;
#pragma unroll
                for (int c1w = 0; c1w < 8; ++c1w) {
                    unsigned bw00 = *reinterpret_cast<const unsigned*>(bbase + c1w * 4);
                    unsigned bw01 = *reinterpret_cast<const unsigned*>(bbase + c1w * 4 + SPT_PITCH);
                    unsigned bw10 = *reinterpret_cast<const unsigned*>(bbase + c1w * 4 + 8 * SPT_PITCH);
                    unsigned bw11 = *reinterpret_cast<const unsigned*>(bbase + c1w * 4 + 9 * SPT_PITCH);
                    const unsigned* ap = abase + c1w * 64;
                    unsigned a00 = ap[0], a01 = ap[8], a10 = ap[16], a11 = ap[24];
                    dp4a(ds[0][0][0], a00, bw00); dp4a(ds[0][0][1], a00, bw01);
                    dp4a(ds[0][0][2], a01, bw00); dp4a(ds[0][0][3], a01, bw01);
                    dp4a(ds[0][1][0], a00, bw10); dp4a(ds[0][1][1], a00, bw11);
                    dp4a(ds[0][1][2], a01, bw10); dp4a(ds[0][1][3], a01, bw11);
                    dp4a(ds[1][0][0], a10, bw00); dp4a(ds[1][0][1], a10, bw01);
                    dp4a(ds[1][0][2], a11, bw00); dp4a(ds[1][0][3], a11, bw01);
                    dp4a(ds[1][1][0], a10, bw10); dp4a(ds[1][1][1], a10, bw11);
                    dp4a(ds[1][1][2], a11, bw10); dp4a(ds[1][1][3], a11, bw11);
                }
            }
        };
        auto fma_phase = [&]() {
            if (t + 1 < TT_) conv1_step(xs[(t + 1) & 1], spt[(t + 1) & 1]);
        };

        // ---- anti-phase scheduling: keep both pipes fed at all times ----
        if (rev) { fma_phase(); alu_phase(); tensor_phase(); }
        else     { tensor_phase(); alu_phase(); fma_phase(); }

        sts_xs(stg, xs[t & 1]);

        // ---- LIF2: q = (hi<<8) + lo(IMMA h0) + lo(dp4a h1), exact integer ----
#pragma unroll
        for (int mt = 0; mt < 2; ++mt)
#pragma unroll
            for (int nt = 0; nt < 2; ++nt)
#pragma unroll
                for (int e = 0; e < 4; ++e) {
                    int hf = e >> 1;
                    int q = dl[mt][nt][e] + ds[mt][nt][e] + (dh[mt][nt][e] << 8);
                    float hval = fmaf((float)q, SCALE, bb[mt][hf]);
                    float vv = v[mt][nt][e];
                    vv = fmaf(hval - vv, INV_TAU, vv);
                    if (vv >= 0.5f) { accs[mt][hf] += 1.f; vv = 0.f; }
                    v[mt][nt][e] = vv;
                }

        __syncthreads();
    }

#pragma unroll
    for (int mt = 0; mt < 2; ++mt)
#pragma unroll
        for (int hf = 0; hf < 2; ++hf) {
            int c2 = c2h * 64 + wy * 32 + mt * 16 + g + hf * 8;
            atomicAdd(&g_pool[b * C2_ + c2], accs[mt][hf]);
        }
}

// ============================================================================
// Kernel E: FC
// ============================================================================
__global__ void fc_kernel(const float* __restrict__ fcw,
                          const float* __restrict__ fcb,
                          float* __restrict__ out) {
    const int tid = threadIdx.x;
    if (tid < B_ * 4) {
        int b = tid >> 2, n = tid & 3;
        float s = 0.f;
#pragma unroll 8
        for (int c = 0; c < C2_; ++c)
            s += g_pool[b * C2_ + c] * fcw[n * C2_ + c];
        out[b * 4 + n] = s * (1.f / (float)(TT_ * LEN_)) + fcb[n];
    }
}

// ============================================================================
extern "C" void kernel_launch(void* const* d_in, const int* in_sizes, int n_in,
                              void* d_out, int out_size) {
    const float* x   = (const float*)d_in[0];
    const float* w1  = (const float*)d_in[1];
    const float* b1  = (const float*)d_in[2];
    const float* w2  = (const float*)d_in[3];
    const float* b2  = (const float*)d_in[4];
    const float* fcw = (const float*)d_in[5];
    const float* fcb = (const float*)d_in[6];
    float* out = (float*)d_out;

    cudaFuncSetAttribute(fused_kernel,
                         cudaFuncAttributeMaxDynamicSharedMemorySize, SMEM_SZ);

    w2prep_kernel<<<28, 256>>>(w2);                                             // 1
    transpose_kernel<<<dim3(TT_ / 32, LEN_ / 32, B_ * CIN_), dim3(32, 8)>>>(x); // 2
    w1prep_kernel<<<16, 256>>>(w1);                                             // 3
    fused_kernel<<<dim3(16, 2, B_), 256, SMEM_SZ>>>(b1, b2);                    // 4 <- ncu
    fc_kernel<<<1, 128>>>(fcw, fcb, out);                                       // 5
}